// round 3
// baseline (speedup 1.0000x reference)
#include <cuda_runtime.h>
#include <cstdint>

// Problem constants
#define B_DIM   64
#define N_DIM   512
#define M_ROWS  (B_DIM * N_DIM)     // 32768
#define EMB     1024
#define NKP     17
#define APP_F   (EMB + NKP)         // 1041
#define ST_F    (4 + 3 * NKP)       // 55
#define KTOT    (APP_F + ST_F)      // 1096
#define KPAD    1104                // next multiple of 16
#define TOK     1024

// GEMM tiling
#define BM 128
#define BN 128
#define BK 16

// Scratch (allowed: __device__ globals, no allocation)
__device__ float g_Wt[KPAD * TOK];   // K-major weights: g_Wt[k*TOK + t]
__device__ float g_bias[TOK];        // app_b + st_b

// ---------------------------------------------------------------------------
// Prologue: build K-major fused weight matrix + fused bias.
// app_W: [TOK, APP_F] row-major; st_W: [TOK, ST_F] row-major.
// ---------------------------------------------------------------------------
__global__ void prep_kernel(const float* __restrict__ app_W,
                            const float* __restrict__ app_b,
                            const float* __restrict__ st_W,
                            const float* __restrict__ st_b)
{
    int tid0   = blockIdx.x * blockDim.x + threadIdx.x;
    int stride = gridDim.x * blockDim.x;

    if (tid0 < TOK) g_bias[tid0] = app_b[tid0] + st_b[tid0];

    for (int i = tid0; i < KPAD * TOK; i += stride) {
        int k = i / TOK;
        int t = i - k * TOK;
        float v = 0.0f;
        if (k < APP_F)      v = app_W[t * APP_F + k];
        else if (k < KTOT)  v = st_W[t * ST_F + (k - APP_F)];
        g_Wt[i] = v;
    }
}

// ---------------------------------------------------------------------------
// Fused masked GEMM: out[r, t] = mask[r] ? feat[r,:] . Wt[:,t] + bias[t] : 0
// feat[r,:] = [emb(1024) | vis(17) | bbox(4) | kp(51)] gathered on the fly.
// 128x128 block tile, 16-deep K tile, 256 threads, 8x8 per-thread microtile.
// ---------------------------------------------------------------------------
__global__ __launch_bounds__(256, 2)
void gemm_kernel(const float* __restrict__ emb,
                 const float* __restrict__ vis,
                 const float* __restrict__ bbox,
                 const float* __restrict__ kp,
                 const unsigned int* __restrict__ mask,
                 float* __restrict__ out)
{
    __shared__ float As[BK][BM];
    __shared__ float Bs[BK][BN];

    const int tid  = threadIdx.x;
    const int tx   = tid & 15;          // 0..15 -> column microtile
    const int ty   = tid >> 4;          // 0..15 -> row microtile
    const int row0 = blockIdx.y * BM;
    const int col0 = blockIdx.x * BN;

    // A-tile loader mapping: 256 threads load 128 rows x 16 k (8 floats each)
    const int lrow = tid >> 1;          // 0..127
    const int lk   = (tid & 1) * 8;     // 0 or 8
    const int r    = row0 + lrow;

    // B-tile loader mapping: 16 k-rows x 128 t (8 floats each, coalesced)
    const int bk = tid >> 4;            // 0..15
    const int bt = (tid & 15) * 8;      // 0..120

    float acc[8][8];
    #pragma unroll
    for (int i = 0; i < 8; i++)
        #pragma unroll
        for (int j = 0; j < 8; j++)
            acc[i][j] = 0.0f;

    for (int k0 = 0; k0 < KPAD; k0 += BK) {
        // ---- load A tile (transposed into As[k][m]) ----
        if (k0 + BK <= EMB) {
            // fast path: entirely inside embeddings, vectorized
            const float4* s = reinterpret_cast<const float4*>(emb + r * EMB + k0 + lk);
            float4 v0 = s[0];
            float4 v1 = s[1];
            As[lk + 0][lrow] = v0.x; As[lk + 1][lrow] = v0.y;
            As[lk + 2][lrow] = v0.z; As[lk + 3][lrow] = v0.w;
            As[lk + 4][lrow] = v1.x; As[lk + 5][lrow] = v1.y;
            As[lk + 6][lrow] = v1.z; As[lk + 7][lrow] = v1.w;
        } else {
            // tail: gather from vis / bbox / kp, zero-pad past KTOT
            #pragma unroll
            for (int j = 0; j < 8; j++) {
                int k = k0 + lk + j;
                float v;
                if (k < EMB)              v = emb[r * EMB + k];
                else if (k < APP_F)       v = vis[r * NKP + (k - EMB)];
                else if (k < APP_F + 4)   v = bbox[r * 4 + (k - APP_F)];
                else if (k < KTOT)        v = kp[r * (3 * NKP) + (k - APP_F - 4)];
                else                      v = 0.0f;
                As[lk + j][lrow] = v;
            }
        }

        // ---- load B tile (already K-major, coalesced float4) ----
        {
            const float4* s = reinterpret_cast<const float4*>(g_Wt + (k0 + bk) * TOK + col0 + bt);
            float4 v0 = s[0];
            float4 v1 = s[1];
            *reinterpret_cast<float4*>(&Bs[bk][bt])     = v0;
            *reinterpret_cast<float4*>(&Bs[bk][bt + 4]) = v1;
        }

        __syncthreads();

        // ---- compute 8x8 microtile over BK k-steps ----
        #pragma unroll
        for (int kk = 0; kk < BK; kk++) {
            float a[8], b[8];
            float4 a0 = *reinterpret_cast<const float4*>(&As[kk][ty * 8]);
            float4 a1 = *reinterpret_cast<const float4*>(&As[kk][ty * 8 + 4]);
            float4 b0 = *reinterpret_cast<const float4*>(&Bs[kk][tx * 8]);
            float4 b1 = *reinterpret_cast<const float4*>(&Bs[kk][tx * 8 + 4]);
            a[0] = a0.x; a[1] = a0.y; a[2] = a0.z; a[3] = a0.w;
            a[4] = a1.x; a[5] = a1.y; a[6] = a1.z; a[7] = a1.w;
            b[0] = b0.x; b[1] = b0.y; b[2] = b0.z; b[3] = b0.w;
            b[4] = b1.x; b[5] = b1.y; b[6] = b1.z; b[7] = b1.w;
            #pragma unroll
            for (int i = 0; i < 8; i++)
                #pragma unroll
                for (int j = 0; j < 8; j++)
                    acc[i][j] = fmaf(a[i], b[j], acc[i][j]);
        }

        __syncthreads();
    }

    // ---- epilogue: bias + mask, vectorized stores ----
    float bb[8];
    #pragma unroll
    for (int j = 0; j < 8; j++) bb[j] = g_bias[col0 + tx * 8 + j];

    #pragma unroll
    for (int i = 0; i < 8; i++) {
        int rr = row0 + ty * 8 + i;
        bool on = (mask[rr] != 0u);
        float4 o0, o1;
        if (on) {
            o0.x = acc[i][0] + bb[0]; o0.y = acc[i][1] + bb[1];
            o0.z = acc[i][2] + bb[2]; o0.w = acc[i][3] + bb[3];
            o1.x = acc[i][4] + bb[4]; o1.y = acc[i][5] + bb[5];
            o1.z = acc[i][6] + bb[6]; o1.w = acc[i][7] + bb[7];
        } else {
            o0 = make_float4(0.f, 0.f, 0.f, 0.f);
            o1 = o0;
        }
        float* dst = out + rr * TOK + col0 + tx * 8;
        *reinterpret_cast<float4*>(dst)     = o0;
        *reinterpret_cast<float4*>(dst + 4) = o1;
    }
}

// ---------------------------------------------------------------------------
extern "C" void kernel_launch(void* const* d_in, const int* in_sizes, int n_in,
                              void* d_out, int out_size)
{
    const float*        emb   = (const float*)d_in[0];
    const float*        vis   = (const float*)d_in[1];
    const float*        bbox  = (const float*)d_in[2];
    const float*        kp    = (const float*)d_in[3];
    const unsigned int* mask  = (const unsigned int*)d_in[4];
    const float*        app_W = (const float*)d_in[5];
    const float*        app_b = (const float*)d_in[6];
    const float*        st_W  = (const float*)d_in[7];
    const float*        st_b  = (const float*)d_in[8];
    float*              out   = (float*)d_out;

    prep_kernel<<<512, 256>>>(app_W, app_b, st_W, st_b);

    dim3 grid(TOK / BN, M_ROWS / BM);   // (8, 256): col-tiles fastest -> A reuse in L2
    gemm_kernel<<<grid, 256>>>(emb, vis, bbox, kp, mask, out);
}

// round 7
// speedup vs baseline: 2.0020x; 2.0020x over previous
#include <cuda_runtime.h>
#include <cuda_fp16.h>
#include <cstdint>

// ---------------------------------------------------------------------------
// Problem constants
// ---------------------------------------------------------------------------
#define M_ROWS  32768           // B*N = 64*512
#define EMB     1024
#define NKP     17
#define APP_F   (EMB + NKP)     // 1041
#define ST_F    (4 + 3 * NKP)   // 55
#define KTOT    (APP_F + ST_F)  // 1096
#define KC      32              // fp16 K elements per pipeline chunk
#define KPAD    1152            // 36 * 32
#define NCHUNK  (KPAD / KC)     // 36
#define TOK     1024

#define TILE_M  128
#define TILE_N  128

// SMEM: padded K-major fp16 tiles, 40 halfs (80B) per row -> conflict-free ldmatrix
#define ROWB    80              // bytes per SMEM row
#define TILE_B  (128 * ROWB)    // 10240 B per operand tile
#define BUF_B   (4 * TILE_B)    // Ah, Al, Bh, Bl
#define SMEM_TOTAL (2 * BUF_B)  // double buffered: 81920 B

// ---------------------------------------------------------------------------
// Device scratch (static globals — no allocation)
// ---------------------------------------------------------------------------
__device__ __half g_Bh[(size_t)TOK * KPAD];   // hi half of fused weights [t][k]
__device__ __half g_Bl[(size_t)TOK * KPAD];   // lo half
__device__ float  g_bias[TOK];                // app_b + st_b

// ---------------------------------------------------------------------------
// PTX helpers (baseline sm_100: ldmatrix / mma.sync / cp.async)
// ---------------------------------------------------------------------------
__device__ __forceinline__ uint32_t smem_u32(const void* p) {
    uint32_t a;
    asm("{ .reg .u64 t; cvta.to.shared.u64 t, %1; cvt.u32.u64 %0, t; }" : "=r"(a) : "l"(p));
    return a;
}

__device__ __forceinline__ void ldmx4(uint32_t* r, uint32_t addr) {
    asm volatile("ldmatrix.sync.aligned.m8n8.x4.shared.b16 {%0,%1,%2,%3}, [%4];"
                 : "=r"(r[0]), "=r"(r[1]), "=r"(r[2]), "=r"(r[3]) : "r"(addr));
}

__device__ __forceinline__ void mma16816(float* c, const uint32_t* a, const uint32_t* b) {
    asm volatile(
        "mma.sync.aligned.m16n8k16.row.col.f32.f16.f16.f32 "
        "{%0,%1,%2,%3}, {%4,%5,%6,%7}, {%8,%9}, {%0,%1,%2,%3};"
        : "+f"(c[0]), "+f"(c[1]), "+f"(c[2]), "+f"(c[3])
        : "r"(a[0]), "r"(a[1]), "r"(a[2]), "r"(a[3]), "r"(b[0]), "r"(b[1]));
}

__device__ __forceinline__ void cp16(uint32_t dst, const void* src) {
    asm volatile("cp.async.cg.shared.global [%0], [%1], 16;" :: "r"(dst), "l"(src) : "memory");
}
__device__ __forceinline__ void cp_commit() {
    asm volatile("cp.async.commit_group;" ::: "memory");
}
__device__ __forceinline__ void cp_wait_all() {
    asm volatile("cp.async.wait_group 0;" ::: "memory");
}

// ---------------------------------------------------------------------------
// Prologue: fused weights -> fp16 hi/lo, K padded to 1152 with zeros; fused bias
// ---------------------------------------------------------------------------
__global__ void prep_W(const float* __restrict__ app_W, const float* __restrict__ app_b,
                       const float* __restrict__ st_W, const float* __restrict__ st_b)
{
    int i0 = blockIdx.x * blockDim.x + threadIdx.x;
    int stride = gridDim.x * blockDim.x;
    if (i0 < TOK) g_bias[i0] = app_b[i0] + st_b[i0];
    for (int i = i0; i < TOK * KPAD; i += stride) {
        int t = i / KPAD;
        int k = i - t * KPAD;
        float v = 0.0f;
        if (k < APP_F)      v = app_W[t * APP_F + k];
        else if (k < KTOT)  v = st_W[t * ST_F + (k - APP_F)];
        __half h = __float2half_rn(v);
        g_Bh[i] = h;
        g_Bl[i] = __float2half_rn(v - __half2float(h));
    }
}

// ---------------------------------------------------------------------------
// Main GEMM: fp16-split HMMA, 128x128 tile, 8 warps (warp tile 64x32),
// K-chunks of 32, double-buffered SMEM. A packing fused into the loader.
// ---------------------------------------------------------------------------
__global__ void __launch_bounds__(256)
gemm_hmma(const float* __restrict__ emb, const float* __restrict__ vis,
          const float* __restrict__ bbox, const float* __restrict__ kp,
          const unsigned int* __restrict__ mask, float* __restrict__ out)
{
    extern __shared__ __align__(128) char smem[];
    const uint32_t sb = smem_u32(smem);

    const int tid    = threadIdx.x;
    const int lane   = tid & 31;
    const int wid    = tid >> 5;
    const int warp_m = (wid & 1) * 64;      // 2 warps along M
    const int warp_n = (wid >> 1) * 32;     // 4 warps along N
    const int row0   = blockIdx.y * TILE_M;
    const int col0   = blockIdx.x * TILE_N;

    // Loader mapping: thread -> (row = tid>>1, 16-float segment = tid&1)
    const int lrow = tid >> 1;
    const int lseg = tid & 1;
    const int grow = row0 + lrow;           // A global row
    const int brow = col0 + lrow;           // B global token

    float acc[4][4][4];
    #pragma unroll
    for (int i = 0; i < 4; i++)
        #pragma unroll
        for (int j = 0; j < 4; j++)
            #pragma unroll
            for (int q = 0; q < 4; q++) acc[i][j][q] = 0.0f;

    // ---- A chunk LDG: 16 fp32 per thread (fast path inside emb, gather tail)
    auto ldgA = [&](float* f, int s) {
        const int k0 = s * KC;
        if (k0 + KC <= EMB) {
            const float4* p = reinterpret_cast<const float4*>(
                emb + (size_t)grow * EMB + k0 + lseg * 16);
            float4 v0 = p[0], v1 = p[1], v2 = p[2], v3 = p[3];
            f[0]=v0.x; f[1]=v0.y; f[2]=v0.z; f[3]=v0.w;
            f[4]=v1.x; f[5]=v1.y; f[6]=v1.z; f[7]=v1.w;
            f[8]=v2.x; f[9]=v2.y; f[10]=v2.z; f[11]=v2.w;
            f[12]=v3.x; f[13]=v3.y; f[14]=v3.z; f[15]=v3.w;
        } else {
            #pragma unroll
            for (int j = 0; j < 16; j++) {
                int k = k0 + lseg * 16 + j;
                float v = 0.0f;
                if (k < EMB)            v = emb[(size_t)grow * EMB + k];
                else if (k < APP_F)     v = vis[(size_t)grow * NKP + (k - EMB)];
                else if (k < APP_F + 4) v = bbox[(size_t)grow * 4 + (k - APP_F)];
                else if (k < KTOT)      v = kp[(size_t)grow * (3*NKP) + (k - APP_F - 4)];
                f[j] = v;
            }
        }
    };

    // ---- A STS: split to hi/lo fp16, two v4.b32 stores per tile
    auto stsA = [&](const float* f, uint32_t buf) {
        uint32_t hi[8], lo[8];
        #pragma unroll
        for (int j = 0; j < 8; j++) {
            __half h0 = __float2half_rn(f[2*j]);
            __half h1 = __float2half_rn(f[2*j+1]);
            __half l0 = __float2half_rn(f[2*j]   - __half2float(h0));
            __half l1 = __float2half_rn(f[2*j+1] - __half2float(h1));
            __half2 H = __halves2half2(h0, h1), L = __halves2half2(l0, l1);
            hi[j] = *reinterpret_cast<uint32_t*>(&H);
            lo[j] = *reinterpret_cast<uint32_t*>(&L);
        }
        uint32_t base = buf + (uint32_t)lrow * ROWB + (uint32_t)lseg * 32;
        asm volatile("st.shared.v4.b32 [%0], {%1,%2,%3,%4};" ::
            "r"(base), "r"(hi[0]), "r"(hi[1]), "r"(hi[2]), "r"(hi[3]) : "memory");
        asm volatile("st.shared.v4.b32 [%0], {%1,%2,%3,%4};" ::
            "r"(base + 16), "r"(hi[4]), "r"(hi[5]), "r"(hi[6]), "r"(hi[7]) : "memory");
        base += TILE_B;   // Al tile
        asm volatile("st.shared.v4.b32 [%0], {%1,%2,%3,%4};" ::
            "r"(base), "r"(lo[0]), "r"(lo[1]), "r"(lo[2]), "r"(lo[3]) : "memory");
        asm volatile("st.shared.v4.b32 [%0], {%1,%2,%3,%4};" ::
            "r"(base + 16), "r"(lo[4]), "r"(lo[5]), "r"(lo[6]), "r"(lo[7]) : "memory");
    };

    // ---- B cp.async: 32 halfs (64B) per row from prepped g_Bh/g_Bl
    auto cpB = [&](int s, uint32_t buf) {
        const int k0 = s * KC;
        uint32_t dst = buf + 2 * TILE_B + (uint32_t)lrow * ROWB + (uint32_t)lseg * 32;
        const __half* sh = g_Bh + (size_t)brow * KPAD + k0 + lseg * 16;
        const __half* sl = g_Bl + (size_t)brow * KPAD + k0 + lseg * 16;
        cp16(dst,              sh);
        cp16(dst + 16,         sh + 8);
        cp16(dst + TILE_B,     sl);
        cp16(dst + TILE_B + 16, sl + 8);
    };

    // ---- compute one 32-deep K chunk from SMEM buffer
    auto compute = [&](uint32_t buf) {
        const uint32_t aH = buf, aL = buf + TILE_B;
        const uint32_t bH = buf + 2*TILE_B, bL = buf + 3*TILE_B;
        const int arow = lane & 15;
        const int nrow = (lane & 7) + ((lane >> 4) << 3);
        #pragma unroll
        for (int k16 = 0; k16 < 2; k16++) {
            const uint32_t akoff = k16 * 32 + ((lane >> 4) << 4);
            const uint32_t bkoff = k16 * 32 + ((lane & 8) << 1);
            uint32_t Ah[4][4], Al[4][4], Bh[4][2], Bl[4][2];
            #pragma unroll
            for (int am = 0; am < 4; am++) {
                uint32_t ro = (uint32_t)(warp_m + am * 16 + arow) * ROWB + akoff;
                ldmx4(Ah[am], aH + ro);
                ldmx4(Al[am], aL + ro);
            }
            #pragma unroll
            for (int bp = 0; bp < 2; bp++) {     // each x4 = 2 n-atoms
                uint32_t ro = (uint32_t)(warp_n + bp * 16 + nrow) * ROWB + bkoff;
                uint32_t r[4];
                ldmx4(r, bH + ro);
                Bh[bp*2][0]=r[0]; Bh[bp*2][1]=r[1]; Bh[bp*2+1][0]=r[2]; Bh[bp*2+1][1]=r[3];
                ldmx4(r, bL + ro);
                Bl[bp*2][0]=r[0]; Bl[bp*2][1]=r[1]; Bl[bp*2+1][0]=r[2]; Bl[bp*2+1][1]=r[3];
            }
            #pragma unroll
            for (int am = 0; am < 4; am++)
                #pragma unroll
                for (int an = 0; an < 4; an++) {
                    mma16816(acc[am][an], Ah[am], Bh[an]);
                    mma16816(acc[am][an], Ah[am], Bl[an]);
                    mma16816(acc[am][an], Al[am], Bh[an]);
                }
        }
    };

    // ---- pipeline: prologue chunk 0
    {
        float f[16];
        ldgA(f, 0);
        cpB(0, sb);
        cp_commit();
        stsA(f, sb);
        cp_wait_all();
        __syncthreads();
    }

    for (int s = 0; s < NCHUNK; s++) {
        const uint32_t cur = sb + (uint32_t)(s & 1) * BUF_B;
        const uint32_t nxt = sb + (uint32_t)((s + 1) & 1) * BUF_B;
        float f[16];
        const bool have = (s + 1 < NCHUNK);
        if (have) {               // issue global loads early; consume after compute
            ldgA(f, s + 1);
            cpB(s + 1, nxt);
            cp_commit();
        }
        compute(cur);
        if (have) {
            stsA(f, nxt);
            cp_wait_all();
        }
        __syncthreads();
    }

    // ---- epilogue: bias + row mask, float2 stores straight from accumulators
    #pragma unroll
    for (int am = 0; am < 4; am++) {
        const int r1 = row0 + warp_m + am * 16 + (lane >> 2);
        const int r2 = r1 + 8;
        const bool m1 = (mask[r1] != 0u);
        const bool m2 = (mask[r2] != 0u);
        #pragma unroll
        for (int an = 0; an < 4; an++) {
            const int cc = col0 + warp_n + an * 8 + 2 * (lane & 3);
            const float b0 = g_bias[cc], b1 = g_bias[cc + 1];
            float2 v1, v2;
            v1.x = m1 ? acc[am][an][0] + b0 : 0.0f;
            v1.y = m1 ? acc[am][an][1] + b1 : 0.0f;
            v2.x = m2 ? acc[am][an][2] + b0 : 0.0f;
            v2.y = m2 ? acc[am][an][3] + b1 : 0.0f;
            *reinterpret_cast<float2*>(out + (size_t)r1 * TOK + cc) = v1;
            *reinterpret_cast<float2*>(out + (size_t)r2 * TOK + cc) = v2;
        }
    }
}

// ---------------------------------------------------------------------------
extern "C" void kernel_launch(void* const* d_in, const int* in_sizes, int n_in,
                              void* d_out, int out_size)
{
    const float*        emb   = (const float*)d_in[0];
    const float*        vis   = (const float*)d_in[1];
    const float*        bbox  = (const float*)d_in[2];
    const float*        kp    = (const float*)d_in[3];
    const unsigned int* mask  = (const unsigned int*)d_in[4];
    const float*        app_W = (const float*)d_in[5];
    const float*        app_b = (const float*)d_in[6];
    const float*        st_W  = (const float*)d_in[7];
    const float*        st_b  = (const float*)d_in[8];
    float*              out   = (float*)d_out;

    cudaFuncSetAttribute(gemm_hmma, cudaFuncAttributeMaxDynamicSharedMemorySize, SMEM_TOTAL);

    prep_W<<<512, 256>>>(app_W, app_b, st_W, st_b);

    dim3 grid(TOK / TILE_N, M_ROWS / TILE_M);   // (8, 256): col-fastest -> A-tile L2 reuse
    gemm_hmma<<<grid, 256, SMEM_TOTAL>>>(emb, vis, bbox, kp, mask, out);
}

// round 8
// speedup vs baseline: 2.2038x; 1.1008x over previous
#include <cuda_runtime.h>
#include <cuda_fp16.h>
#include <cstdint>

// ---------------------------------------------------------------------------
// Problem constants
// ---------------------------------------------------------------------------
#define M_ROWS  32768           // B*N = 64*512
#define EMB     1024
#define NKP     17
#define APP_F   (EMB + NKP)     // 1041
#define ST_F    (4 + 3 * NKP)   // 55
#define KTOT    (APP_F + ST_F)  // 1096
#define KC      32              // fp16 K elements per pipeline chunk
#define KPAD    1152            // 36 * 32
#define NCHUNK  (KPAD / KC)     // 36
#define TOK     1024

#define TILE_M  128
#define TILE_N  128

// SMEM: padded K-major fp16 tiles, 40 halfs (80B) per row -> conflict-free ldmatrix
#define ROWB    80              // bytes per SMEM row
#define TILE_B  (128 * ROWB)    // 10240 B per operand tile
#define BUF_B   (4 * TILE_B)    // Ah, Al, Bh, Bl
#define SMEM_TOTAL (2 * BUF_B)  // double buffered: 81920 B (-> 2 CTAs/SM)

// ---------------------------------------------------------------------------
// Device scratch (static globals — no allocation)
// ---------------------------------------------------------------------------
__device__ __half g_Ah[(size_t)M_ROWS * KPAD];   // hi half of features, K-major
__device__ __half g_Al[(size_t)M_ROWS * KPAD];   // lo half
__device__ __half g_Bh[(size_t)TOK * KPAD];      // hi half of fused weights [t][k]
__device__ __half g_Bl[(size_t)TOK * KPAD];      // lo half
__device__ float  g_bias[TOK];                   // app_b + st_b

// ---------------------------------------------------------------------------
// PTX helpers (baseline sm_100: ldmatrix / mma.sync / cp.async)
// ---------------------------------------------------------------------------
__device__ __forceinline__ uint32_t smem_u32(const void* p) {
    uint32_t a;
    asm("{ .reg .u64 t; cvta.to.shared.u64 t, %1; cvt.u32.u64 %0, t; }" : "=r"(a) : "l"(p));
    return a;
}

__device__ __forceinline__ void ldmx4(uint32_t* r, uint32_t addr) {
    asm volatile("ldmatrix.sync.aligned.m8n8.x4.shared.b16 {%0,%1,%2,%3}, [%4];"
                 : "=r"(r[0]), "=r"(r[1]), "=r"(r[2]), "=r"(r[3]) : "r"(addr));
}

__device__ __forceinline__ void mma16816(float* c, const uint32_t* a, const uint32_t* b) {
    asm volatile(
        "mma.sync.aligned.m16n8k16.row.col.f32.f16.f16.f32 "
        "{%0,%1,%2,%3}, {%4,%5,%6,%7}, {%8,%9}, {%0,%1,%2,%3};"
        : "+f"(c[0]), "+f"(c[1]), "+f"(c[2]), "+f"(c[3])
        : "r"(a[0]), "r"(a[1]), "r"(a[2]), "r"(a[3]), "r"(b[0]), "r"(b[1]));
}

__device__ __forceinline__ void cp16(uint32_t dst, const void* src) {
    asm volatile("cp.async.cg.shared.global [%0], [%1], 16;" :: "r"(dst), "l"(src) : "memory");
}
__device__ __forceinline__ void cp_commit() {
    asm volatile("cp.async.commit_group;" ::: "memory");
}
__device__ __forceinline__ void cp_wait_all() {
    asm volatile("cp.async.wait_group 0;" ::: "memory");
}

// ---------------------------------------------------------------------------
// Prologue 1: fused weights -> fp16 hi/lo, K padded to 1152; fused bias.
// One block per token row; k-coalesced.
// ---------------------------------------------------------------------------
__global__ void prep_W(const float* __restrict__ app_W, const float* __restrict__ app_b,
                       const float* __restrict__ st_W, const float* __restrict__ st_b)
{
    const int t = blockIdx.x;
    if (threadIdx.x == 0) g_bias[t] = app_b[t] + st_b[t];
    for (int k = threadIdx.x; k < KPAD; k += blockDim.x) {
        float v = 0.0f;
        if (k < APP_F)      v = app_W[t * APP_F + k];
        else if (k < KTOT)  v = st_W[t * ST_F + (k - APP_F)];
        __half h = __float2half_rn(v);
        g_Bh[(size_t)t * KPAD + k] = h;
        g_Bl[(size_t)t * KPAD + k] = __float2half_rn(v - __half2float(h));
    }
}

// ---------------------------------------------------------------------------
// Prologue 2: gather concatenated features -> fp16 hi/lo [M_ROWS][KPAD].
// One block per feature row; k-coalesced reads and writes.
// ---------------------------------------------------------------------------
__global__ void prep_A(const float* __restrict__ emb, const float* __restrict__ vis,
                       const float* __restrict__ bbox, const float* __restrict__ kp)
{
    const int r = blockIdx.x;
    for (int k = threadIdx.x; k < KPAD; k += blockDim.x) {
        float v = 0.0f;
        if (k < EMB)            v = emb[(size_t)r * EMB + k];
        else if (k < APP_F)     v = vis[(size_t)r * NKP + (k - EMB)];
        else if (k < APP_F + 4) v = bbox[(size_t)r * 4 + (k - APP_F)];
        else if (k < KTOT)      v = kp[(size_t)r * (3 * NKP) + (k - APP_F - 4)];
        __half h = __float2half_rn(v);
        g_Ah[(size_t)r * KPAD + k] = h;
        g_Al[(size_t)r * KPAD + k] = __float2half_rn(v - __half2float(h));
    }
}

// ---------------------------------------------------------------------------
// Main GEMM: fp16-split HMMA (C = Ah*Bh + Ah*Bl + Al*Bh, fp32 accum),
// 128x128 tile, 8 warps (warp tile 64x32), K-chunks of 32.
// All four operand tiles loaded via cp.async (zero loader register cost),
// double-buffered; 2 CTAs/SM for latency hiding.
// ---------------------------------------------------------------------------
__global__ void __launch_bounds__(256, 2)
gemm_hmma(const unsigned int* __restrict__ mask, float* __restrict__ out)
{
    extern __shared__ __align__(128) char smem[];
    const uint32_t sb = smem_u32(smem);

    const int tid    = threadIdx.x;
    const int lane   = tid & 31;
    const int wid    = tid >> 5;
    const int warp_m = (wid & 1) * 64;      // 2 warps along M
    const int warp_n = (wid >> 1) * 32;     // 4 warps along N
    const int row0   = blockIdx.y * TILE_M;
    const int col0   = blockIdx.x * TILE_N;

    // Loader mapping: thread -> (row = tid>>1, 32B segment = tid&1)
    const int lrow = tid >> 1;
    const int lseg = tid & 1;
    const size_t aoff = (size_t)(row0 + lrow) * KPAD + lseg * 16;
    const size_t boff = (size_t)(col0 + lrow) * KPAD + lseg * 16;

    float acc[4][4][4];
    #pragma unroll
    for (int i = 0; i < 4; i++)
        #pragma unroll
        for (int j = 0; j < 4; j++)
            #pragma unroll
            for (int q = 0; q < 4; q++) acc[i][j][q] = 0.0f;

    // ---- async-load one 32-deep K chunk (Ah, Al, Bh, Bl) into buffer
    auto cpAll = [&](int s, uint32_t buf) {
        const int k0 = s * KC;
        const uint32_t d = buf + (uint32_t)lrow * ROWB + (uint32_t)lseg * 32;
        const __half* pAh = g_Ah + aoff + k0;
        const __half* pAl = g_Al + aoff + k0;
        const __half* pBh = g_Bh + boff + k0;
        const __half* pBl = g_Bl + boff + k0;
        cp16(d,                   pAh);   cp16(d + 16,              pAh + 8);
        cp16(d + TILE_B,          pAl);   cp16(d + TILE_B + 16,     pAl + 8);
        cp16(d + 2 * TILE_B,      pBh);   cp16(d + 2 * TILE_B + 16, pBh + 8);
        cp16(d + 3 * TILE_B,      pBl);   cp16(d + 3 * TILE_B + 16, pBl + 8);
    };

    // ---- compute one 32-deep K chunk from SMEM buffer
    auto compute = [&](uint32_t buf) {
        const uint32_t aH = buf, aL = buf + TILE_B;
        const uint32_t bH = buf + 2 * TILE_B, bL = buf + 3 * TILE_B;
        const int arow = lane & 15;
        const int nrow = (lane & 7) + ((lane >> 4) << 3);
        #pragma unroll
        for (int k16 = 0; k16 < 2; k16++) {
            const uint32_t akoff = k16 * 32 + ((lane >> 4) << 4);
            const uint32_t bkoff = k16 * 32 + ((lane & 8) << 1);
            uint32_t Ah[4][4], Al[4][4], Bh[4][2], Bl[4][2];
            #pragma unroll
            for (int am = 0; am < 4; am++) {
                uint32_t ro = (uint32_t)(warp_m + am * 16 + arow) * ROWB + akoff;
                ldmx4(Ah[am], aH + ro);
                ldmx4(Al[am], aL + ro);
            }
            #pragma unroll
            for (int bp = 0; bp < 2; bp++) {     // each x4 = 2 n-atoms
                uint32_t ro = (uint32_t)(warp_n + bp * 16 + nrow) * ROWB + bkoff;
                uint32_t r[4];
                ldmx4(r, bH + ro);
                Bh[bp*2][0]=r[0]; Bh[bp*2][1]=r[1]; Bh[bp*2+1][0]=r[2]; Bh[bp*2+1][1]=r[3];
                ldmx4(r, bL + ro);
                Bl[bp*2][0]=r[0]; Bl[bp*2][1]=r[1]; Bl[bp*2+1][0]=r[2]; Bl[bp*2+1][1]=r[3];
            }
            #pragma unroll
            for (int am = 0; am < 4; am++)
                #pragma unroll
                for (int an = 0; an < 4; an++) {
                    mma16816(acc[am][an], Ah[am], Bh[an]);
                    mma16816(acc[am][an], Ah[am], Bl[an]);
                    mma16816(acc[am][an], Al[am], Bh[an]);
                }
        }
    };

    // ---- pipeline: prologue chunk 0
    cpAll(0, sb);
    cp_commit();
    cp_wait_all();
    __syncthreads();

    for (int s = 0; s < NCHUNK; s++) {
        const uint32_t cur = sb + (uint32_t)(s & 1) * BUF_B;
        const uint32_t nxt = sb + (uint32_t)((s + 1) & 1) * BUF_B;
        const bool have = (s + 1 < NCHUNK);
        if (have) {
            cpAll(s + 1, nxt);      // async fill of other buffer during compute
            cp_commit();
        }
        compute(cur);
        if (have) cp_wait_all();
        __syncthreads();
    }

    // ---- epilogue: bias + row mask, float2 stores straight from accumulators
    #pragma unroll
    for (int am = 0; am < 4; am++) {
        const int r1 = row0 + warp_m + am * 16 + (lane >> 2);
        const int r2 = r1 + 8;
        const bool m1 = (mask[r1] != 0u);
        const bool m2 = (mask[r2] != 0u);
        #pragma unroll
        for (int an = 0; an < 4; an++) {
            const int cc = col0 + warp_n + an * 8 + 2 * (lane & 3);
            const float b0 = g_bias[cc], b1 = g_bias[cc + 1];
            float2 v1, v2;
            v1.x = m1 ? acc[am][an][0] + b0 : 0.0f;
            v1.y = m1 ? acc[am][an][1] + b1 : 0.0f;
            v2.x = m2 ? acc[am][an][2] + b0 : 0.0f;
            v2.y = m2 ? acc[am][an][3] + b1 : 0.0f;
            *reinterpret_cast<float2*>(out + (size_t)r1 * TOK + cc) = v1;
            *reinterpret_cast<float2*>(out + (size_t)r2 * TOK + cc) = v2;
        }
    }
}

// ---------------------------------------------------------------------------
extern "C" void kernel_launch(void* const* d_in, const int* in_sizes, int n_in,
                              void* d_out, int out_size)
{
    const float*        emb   = (const float*)d_in[0];
    const float*        vis   = (const float*)d_in[1];
    const float*        bbox  = (const float*)d_in[2];
    const float*        kp    = (const float*)d_in[3];
    const unsigned int* mask  = (const unsigned int*)d_in[4];
    const float*        app_W = (const float*)d_in[5];
    const float*        app_b = (const float*)d_in[6];
    const float*        st_W  = (const float*)d_in[7];
    const float*        st_b  = (const float*)d_in[8];
    float*              out   = (float*)d_out;

    cudaFuncSetAttribute(gemm_hmma, cudaFuncAttributeMaxDynamicSharedMemorySize, SMEM_TOTAL);

    prep_W<<<TOK, 256>>>(app_W, app_b, st_W, st_b);
    prep_A<<<M_ROWS, 128>>>(emb, vis, bbox, kp);

    dim3 grid(TOK / TILE_N, M_ROWS / TILE_M);   // (8, 256): col-fastest -> A-tile L2 reuse
    gemm_hmma<<<grid, 256, SMEM_TOTAL>>>(mask, out);
}

// round 9
// speedup vs baseline: 3.1638x; 1.4356x over previous
#include <cuda_runtime.h>
#include <cuda_fp16.h>
#include <cstdint>

// ---------------------------------------------------------------------------
// Problem constants
// ---------------------------------------------------------------------------
#define M_ROWS  32768           // B*N = 64*512
#define EMB     1024
#define NKP     17
#define APP_F   (EMB + NKP)     // 1041
#define ST_F    (4 + 3 * NKP)   // 55
#define KTOT    (APP_F + ST_F)  // 1096
#define KC      32              // fp16 K elements per pipeline chunk
#define KPAD    1152            // 36 * 32
#define NCHUNK  (KPAD / KC)     // 36
#define TOK     1024

#define TILE_M  128
#define TILE_N  128

// SMEM: padded K-major fp16 tiles, 40 halfs (80B) per row -> conflict-free ldmatrix
#define ROWB    80              // bytes per SMEM row
#define TILE_B  (128 * ROWB)    // 10240 B per operand tile
#define STAGE_B (3 * TILE_B)    // Ah, Bh, Bl per stage: 30720 B
#define NSTAGE  3
#define SMEM_TOTAL (NSTAGE * STAGE_B)   // 92160 B; x2 CTAs = 180 KB < 227 KB

// ---------------------------------------------------------------------------
// Device scratch (static globals — no allocation)
// ---------------------------------------------------------------------------
__device__ __half g_Ah[(size_t)M_ROWS * KPAD];   // fp16 features, K-major (hi only)
__device__ __half g_Bh[(size_t)TOK * KPAD];      // hi half of fused weights [t][k]
__device__ __half g_Bl[(size_t)TOK * KPAD];      // lo half (B = Bh + Bl to ~2^-22)
__device__ float  g_bias[TOK];                   // app_b + st_b

// ---------------------------------------------------------------------------
// PTX helpers (baseline sm_100: ldmatrix / mma.sync / cp.async)
// ---------------------------------------------------------------------------
__device__ __forceinline__ uint32_t smem_u32(const void* p) {
    uint32_t a;
    asm("{ .reg .u64 t; cvta.to.shared.u64 t, %1; cvt.u32.u64 %0, t; }" : "=r"(a) : "l"(p));
    return a;
}

__device__ __forceinline__ void ldmx4(uint32_t* r, uint32_t addr) {
    asm volatile("ldmatrix.sync.aligned.m8n8.x4.shared.b16 {%0,%1,%2,%3}, [%4];"
                 : "=r"(r[0]), "=r"(r[1]), "=r"(r[2]), "=r"(r[3]) : "r"(addr));
}

__device__ __forceinline__ void mma16816(float* c, const uint32_t* a, const uint32_t* b) {
    asm volatile(
        "mma.sync.aligned.m16n8k16.row.col.f32.f16.f16.f32 "
        "{%0,%1,%2,%3}, {%4,%5,%6,%7}, {%8,%9}, {%0,%1,%2,%3};"
        : "+f"(c[0]), "+f"(c[1]), "+f"(c[2]), "+f"(c[3])
        : "r"(a[0]), "r"(a[1]), "r"(a[2]), "r"(a[3]), "r"(b[0]), "r"(b[1]));
}

__device__ __forceinline__ void cp16(uint32_t dst, const void* src) {
    asm volatile("cp.async.cg.shared.global [%0], [%1], 16;" :: "r"(dst), "l"(src) : "memory");
}
__device__ __forceinline__ void cp_commit() {
    asm volatile("cp.async.commit_group;" ::: "memory");
}
template <int N>
__device__ __forceinline__ void cp_wait() {
    asm volatile("cp.async.wait_group %0;" :: "n"(N) : "memory");
}

// ---------------------------------------------------------------------------
// Prologue 1: fused weights -> fp16 hi/lo, K padded to 1152; fused bias.
// ---------------------------------------------------------------------------
__global__ void prep_W(const float* __restrict__ app_W, const float* __restrict__ app_b,
                       const float* __restrict__ st_W, const float* __restrict__ st_b)
{
    const int t = blockIdx.x;
    if (threadIdx.x == 0) g_bias[t] = app_b[t] + st_b[t];
    for (int k = threadIdx.x; k < KPAD; k += blockDim.x) {
        float v = 0.0f;
        if (k < APP_F)      v = app_W[t * APP_F + k];
        else if (k < KTOT)  v = st_W[t * ST_F + (k - APP_F)];
        __half h = __float2half_rn(v);
        g_Bh[(size_t)t * KPAD + k] = h;
        g_Bl[(size_t)t * KPAD + k] = __float2half_rn(v - __half2float(h));
    }
}

// ---------------------------------------------------------------------------
// Prologue 2: gather concatenated features -> fp16 [M_ROWS][KPAD] (hi only).
// ---------------------------------------------------------------------------
__global__ void prep_A(const float* __restrict__ emb, const float* __restrict__ vis,
                       const float* __restrict__ bbox, const float* __restrict__ kp)
{
    const int r = blockIdx.x;
    for (int k = threadIdx.x; k < KPAD; k += blockDim.x) {
        float v = 0.0f;
        if (k < EMB)            v = emb[(size_t)r * EMB + k];
        else if (k < APP_F)     v = vis[(size_t)r * NKP + (k - EMB)];
        else if (k < APP_F + 4) v = bbox[(size_t)r * 4 + (k - APP_F)];
        else if (k < KTOT)      v = kp[(size_t)r * (3 * NKP) + (k - APP_F - 4)];
        g_Ah[(size_t)r * KPAD + k] = __float2half_rn(v);
    }
}

// ---------------------------------------------------------------------------
// Main GEMM: one-sided fp16 split  C = Ah*Bh + Ah*Bl  (fp32 accumulate).
// 128x128 tile, 8 warps (warp tile 64x32), K-chunks of 32.
// 3-stage cp.async pipeline (prefetch distance 2), 2 CTAs/SM.
// ---------------------------------------------------------------------------
__global__ void __launch_bounds__(256, 2)
gemm_hmma(const unsigned int* __restrict__ mask, float* __restrict__ out)
{
    extern __shared__ __align__(128) char smem[];
    const uint32_t sb = smem_u32(smem);

    const int tid    = threadIdx.x;
    const int lane   = tid & 31;
    const int wid    = tid >> 5;
    const int warp_m = (wid & 1) * 64;      // 2 warps along M
    const int warp_n = (wid >> 1) * 32;     // 4 warps along N
    const int row0   = blockIdx.y * TILE_M;
    const int col0   = blockIdx.x * TILE_N;

    // Loader mapping: thread -> (row = tid>>1, 32B segment = tid&1)
    const int lrow = tid >> 1;
    const int lseg = tid & 1;
    const size_t aoff = (size_t)(row0 + lrow) * KPAD + lseg * 16;
    const size_t boff = (size_t)(col0 + lrow) * KPAD + lseg * 16;

    float acc[4][4][4];
    #pragma unroll
    for (int i = 0; i < 4; i++)
        #pragma unroll
        for (int j = 0; j < 4; j++)
            #pragma unroll
            for (int q = 0; q < 4; q++) acc[i][j][q] = 0.0f;

    // ---- async-load one 32-deep K chunk (Ah, Bh, Bl) into stage buffer
    auto cpAll = [&](int s, uint32_t buf) {
        const int k0 = s * KC;
        const uint32_t d = buf + (uint32_t)lrow * ROWB + (uint32_t)lseg * 32;
        const __half* pA  = g_Ah + aoff + k0;
        const __half* pBh = g_Bh + boff + k0;
        const __half* pBl = g_Bl + boff + k0;
        cp16(d,                  pA);    cp16(d + 16,             pA + 8);
        cp16(d + TILE_B,         pBh);   cp16(d + TILE_B + 16,    pBh + 8);
        cp16(d + 2 * TILE_B,     pBl);   cp16(d + 2 * TILE_B + 16, pBl + 8);
    };

    // ---- compute one 32-deep K chunk from a stage buffer
    auto compute = [&](uint32_t buf) {
        const uint32_t aH = buf;
        const uint32_t bH = buf + TILE_B, bL = buf + 2 * TILE_B;
        const int arow = lane & 15;
        const int nrow = (lane & 7) + ((lane >> 4) << 3);
        #pragma unroll
        for (int k16 = 0; k16 < 2; k16++) {
            const uint32_t akoff = k16 * 32 + ((lane >> 4) << 4);
            const uint32_t bkoff = k16 * 32 + ((lane & 8) << 1);
            uint32_t Ah[4][4], Bh[4][2], Bl[4][2];
            #pragma unroll
            for (int am = 0; am < 4; am++) {
                uint32_t ro = (uint32_t)(warp_m + am * 16 + arow) * ROWB + akoff;
                ldmx4(Ah[am], aH + ro);
            }
            #pragma unroll
            for (int bp = 0; bp < 2; bp++) {     // each x4 = 2 n-atoms
                uint32_t ro = (uint32_t)(warp_n + bp * 16 + nrow) * ROWB + bkoff;
                uint32_t r[4];
                ldmx4(r, bH + ro);
                Bh[bp*2][0]=r[0]; Bh[bp*2][1]=r[1]; Bh[bp*2+1][0]=r[2]; Bh[bp*2+1][1]=r[3];
                ldmx4(r, bL + ro);
                Bl[bp*2][0]=r[0]; Bl[bp*2][1]=r[1]; Bl[bp*2+1][0]=r[2]; Bl[bp*2+1][1]=r[3];
            }
            #pragma unroll
            for (int am = 0; am < 4; am++)
                #pragma unroll
                for (int an = 0; an < 4; an++) {
                    mma16816(acc[am][an], Ah[am], Bh[an]);
                    mma16816(acc[am][an], Ah[am], Bl[an]);
                }
        }
    };

    // ---- 3-stage pipeline: prefetch chunks 0 and 1
    cpAll(0, sb + 0 * STAGE_B); cp_commit();
    cpAll(1, sb + 1 * STAGE_B); cp_commit();

    for (int s = 0; s < NCHUNK; s++) {
        cp_wait<1>();               // oldest outstanding group (chunk s) complete
        __syncthreads();            // visibility + all warps done with stage (s-1)%3
        if (s + 2 < NCHUNK) {       // prefetch into stage (s+2)%3 == (s-1)%3
            cpAll(s + 2, sb + (uint32_t)((s + 2) % NSTAGE) * STAGE_B);
            cp_commit();
        }
        compute(sb + (uint32_t)(s % NSTAGE) * STAGE_B);
    }

    // ---- epilogue: bias + row mask, float2 stores straight from accumulators
    #pragma unroll
    for (int am = 0; am < 4; am++) {
        const int r1 = row0 + warp_m + am * 16 + (lane >> 2);
        const int r2 = r1 + 8;
        const bool m1 = (mask[r1] != 0u);
        const bool m2 = (mask[r2] != 0u);
        #pragma unroll
        for (int an = 0; an < 4; an++) {
            const int cc = col0 + warp_n + an * 8 + 2 * (lane & 3);
            const float b0 = g_bias[cc], b1 = g_bias[cc + 1];
            float2 v1, v2;
            v1.x = m1 ? acc[am][an][0] + b0 : 0.0f;
            v1.y = m1 ? acc[am][an][1] + b1 : 0.0f;
            v2.x = m2 ? acc[am][an][2] + b0 : 0.0f;
            v2.y = m2 ? acc[am][an][3] + b1 : 0.0f;
            *reinterpret_cast<float2*>(out + (size_t)r1 * TOK + cc) = v1;
            *reinterpret_cast<float2*>(out + (size_t)r2 * TOK + cc) = v2;
        }
    }
}

// ---------------------------------------------------------------------------
extern "C" void kernel_launch(void* const* d_in, const int* in_sizes, int n_in,
                              void* d_out, int out_size)
{
    const float*        emb   = (const float*)d_in[0];
    const float*        vis   = (const float*)d_in[1];
    const float*        bbox  = (const float*)d_in[2];
    const float*        kp    = (const float*)d_in[3];
    const unsigned int* mask  = (const unsigned int*)d_in[4];
    const float*        app_W = (const float*)d_in[5];
    const float*        app_b = (const float*)d_in[6];
    const float*        st_W  = (const float*)d_in[7];
    const float*        st_b  = (const float*)d_in[8];
    float*              out   = (float*)d_out;

    cudaFuncSetAttribute(gemm_hmma, cudaFuncAttributeMaxDynamicSharedMemorySize, SMEM_TOTAL);

    prep_W<<<TOK, 256>>>(app_W, app_b, st_W, st_b);
    prep_A<<<M_ROWS, 128>>>(emb, vis, bbox, kp);

    dim3 grid(TOK / TILE_N, M_ROWS / TILE_M);   // (8, 256): col-fastest -> A-tile L2 reuse
    gemm_hmma<<<grid, 256, SMEM_TOTAL>>>(mask, out);
}

// round 10
// speedup vs baseline: 3.4610x; 1.0939x over previous
#include <cuda_runtime.h>
#include <cuda_fp16.h>
#include <cstdint>

// ---------------------------------------------------------------------------
// Problem constants
// ---------------------------------------------------------------------------
#define M_ROWS  32768           // B*N = 64*512
#define EMB     1024
#define NKP     17
#define APP_F   (EMB + NKP)     // 1041
#define ST_F    (4 + 3 * NKP)   // 55
#define KTOT    (APP_F + ST_F)  // 1096
#define KC      64              // fp16 K elements per pipeline chunk (128B row)
#define KPAD    1152            // 18 * 64
#define NCHUNK  (KPAD / KC)     // 18
#define TOK     1024

#define TILE_M  128
#define TILE_N  128

// SMEM: XOR-swizzled 128B rows (no padding). tile = 128 rows * 128B = 16 KB.
#define ROWB    128
#define TILE_B  (128 * ROWB)            // 16384 B per operand tile
#define STAGE_B (3 * TILE_B)            // Ah, Bh, Bl per stage: 49152 B
#define NSTAGE  2
#define SMEM_TOTAL (NSTAGE * STAGE_B)   // 98304 B; x2 CTAs = 192 KB < 227 KB

// ---------------------------------------------------------------------------
// Device scratch (static globals — no allocation)
// ---------------------------------------------------------------------------
__device__ __half g_Ah[(size_t)M_ROWS * KPAD];   // fp16 features, K-major
__device__ __half g_Bh[(size_t)TOK * KPAD];      // hi half of fused weights [t][k]
__device__ __half g_Bl[(size_t)TOK * KPAD];      // lo half (B = Bh + Bl to ~2^-22)
__device__ float  g_bias[TOK];                   // app_b + st_b

// ---------------------------------------------------------------------------
// PTX helpers (baseline sm_100: ldmatrix / mma.sync / cp.async)
// ---------------------------------------------------------------------------
__device__ __forceinline__ uint32_t smem_u32(const void* p) {
    uint32_t a;
    asm("{ .reg .u64 t; cvta.to.shared.u64 t, %1; cvt.u32.u64 %0, t; }" : "=r"(a) : "l"(p));
    return a;
}

__device__ __forceinline__ void ldmx4(uint32_t* r, uint32_t addr) {
    asm volatile("ldmatrix.sync.aligned.m8n8.x4.shared.b16 {%0,%1,%2,%3}, [%4];"
                 : "=r"(r[0]), "=r"(r[1]), "=r"(r[2]), "=r"(r[3]) : "r"(addr));
}

__device__ __forceinline__ void mma16816(float* c, const uint32_t* a, const uint32_t* b) {
    asm volatile(
        "mma.sync.aligned.m16n8k16.row.col.f32.f16.f16.f32 "
        "{%0,%1,%2,%3}, {%4,%5,%6,%7}, {%8,%9}, {%0,%1,%2,%3};"
        : "+f"(c[0]), "+f"(c[1]), "+f"(c[2]), "+f"(c[3])
        : "r"(a[0]), "r"(a[1]), "r"(a[2]), "r"(a[3]), "r"(b[0]), "r"(b[1]));
}

__device__ __forceinline__ void cp16(uint32_t dst, const void* src) {
    asm volatile("cp.async.cg.shared.global [%0], [%1], 16;" :: "r"(dst), "l"(src) : "memory");
}
__device__ __forceinline__ void cp_commit() {
    asm volatile("cp.async.commit_group;" ::: "memory");
}
template <int N>
__device__ __forceinline__ void cp_wait() {
    asm volatile("cp.async.wait_group %0;" :: "n"(N) : "memory");
}

// Swizzle: 16B chunk index within a 128B row, XORed with (row & 7).
// Conflict-free for both the cp.async stores and all ldmatrix read phases.
__device__ __forceinline__ uint32_t sw_off(uint32_t row, uint32_t c16) {
    return row * ROWB + ((c16 ^ (row & 7u)) << 4);
}

// ---------------------------------------------------------------------------
// Fused prologue. Blocks [0, M_ROWS): pack features row -> g_Ah (fp16).
// Blocks [M_ROWS, M_ROWS+TOK): pack weights row -> g_Bh/g_Bl + fused bias.
// 128 threads per block.
// ---------------------------------------------------------------------------
__global__ void prep_all(const float* __restrict__ emb, const float* __restrict__ vis,
                         const float* __restrict__ bbox, const float* __restrict__ kp,
                         const float* __restrict__ app_W, const float* __restrict__ app_b,
                         const float* __restrict__ st_W, const float* __restrict__ st_b)
{
    const int blk = blockIdx.x;
    const int tid = threadIdx.x;

    if (blk < M_ROWS) {
        const int r = blk;
        // Embedding part: thread t handles halfs [8t, 8t+8): 2x float4 -> uint4
        const float4* s = reinterpret_cast<const float4*>(emb + (size_t)r * EMB + tid * 8);
        float4 v0 = s[0], v1 = s[1];
        __half2 h0 = __floats2half2_rn(v0.x, v0.y);
        __half2 h1 = __floats2half2_rn(v0.z, v0.w);
        __half2 h2 = __floats2half2_rn(v1.x, v1.y);
        __half2 h3 = __floats2half2_rn(v1.z, v1.w);
        uint4 pk;
        pk.x = *reinterpret_cast<uint32_t*>(&h0);
        pk.y = *reinterpret_cast<uint32_t*>(&h1);
        pk.z = *reinterpret_cast<uint32_t*>(&h2);
        pk.w = *reinterpret_cast<uint32_t*>(&h3);
        *reinterpret_cast<uint4*>(g_Ah + (size_t)r * KPAD + tid * 8) = pk;
        // Tail part: k in [1024, 1152), one element per thread
        const int k = EMB + tid;
        float v = 0.0f;
        if (k < APP_F)          v = vis[(size_t)r * NKP + (k - EMB)];
        else if (k < APP_F + 4) v = bbox[(size_t)r * 4 + (k - APP_F)];
        else if (k < KTOT)      v = kp[(size_t)r * (3 * NKP) + (k - APP_F - 4)];
        g_Ah[(size_t)r * KPAD + k] = __float2half_rn(v);
    } else {
        const int t = blk - M_ROWS;
        if (tid == 0) g_bias[t] = app_b[t] + st_b[t];
        for (int k = tid; k < KPAD; k += 128) {
            float v = 0.0f;
            if (k < APP_F)      v = app_W[t * APP_F + k];
            else if (k < KTOT)  v = st_W[t * ST_F + (k - APP_F)];
            __half h = __float2half_rn(v);
            g_Bh[(size_t)t * KPAD + k] = h;
            g_Bl[(size_t)t * KPAD + k] = __float2half_rn(v - __half2float(h));
        }
    }
}

// ---------------------------------------------------------------------------
// Main GEMM: one-sided fp16 split  C = Ah*Bh + Ah*Bl  (fp32 accumulate).
// 128x128 tile, 8 warps (warp tile 64x32), K-chunks of 64, swizzled SMEM,
// 2-stage cp.async pipeline, 2 CTAs/SM.
// ---------------------------------------------------------------------------
__global__ void __launch_bounds__(256, 2)
gemm_hmma(const unsigned int* __restrict__ mask, float* __restrict__ out)
{
    extern __shared__ __align__(128) char smem[];
    const uint32_t sb = smem_u32(smem);

    const int tid    = threadIdx.x;
    const int lane   = tid & 31;
    const int wid    = tid >> 5;
    const int warp_m = (wid & 1) * 64;      // 2 warps along M
    const int warp_n = (wid >> 1) * 32;     // 4 warps along N
    const int row0   = blockIdx.y * TILE_M;
    const int col0   = blockIdx.x * TILE_N;

    // Loader mapping: thread -> (row = tid>>1, four 16B chunks at c0 = (tid&1)*4)
    const int lrow = tid >> 1;
    const int lc0  = (tid & 1) * 4;
    const size_t aoff = (size_t)(row0 + lrow) * KPAD;
    const size_t boff = (size_t)(col0 + lrow) * KPAD;

    float acc[4][4][4];
    #pragma unroll
    for (int i = 0; i < 4; i++)
        #pragma unroll
        for (int j = 0; j < 4; j++)
            #pragma unroll
            for (int q = 0; q < 4; q++) acc[i][j][q] = 0.0f;

    // ---- async-load one 64-deep K chunk (Ah, Bh, Bl) into a stage buffer
    auto cpAll = [&](int s, uint32_t buf) {
        const int k0 = s * KC;
        #pragma unroll
        for (int i = 0; i < 4; i++) {
            const uint32_t c = (uint32_t)(lc0 + i);
            const uint32_t d = buf + sw_off((uint32_t)lrow, c);
            cp16(d,              g_Ah + aoff + k0 + c * 8);
            cp16(d + TILE_B,     g_Bh + boff + k0 + c * 8);
            cp16(d + 2 * TILE_B, g_Bl + boff + k0 + c * 8);
        }
    };

    // ---- compute one 64-deep K chunk from a stage buffer
    auto compute = [&](uint32_t buf) {
        const uint32_t aH = buf;
        const uint32_t bH = buf + TILE_B, bL = buf + 2 * TILE_B;
        const uint32_t arow = (uint32_t)(lane & 15);
        const uint32_t nrow = (uint32_t)((lane & 7) + ((lane >> 4) << 3));
        #pragma unroll
        for (int k16 = 0; k16 < 4; k16++) {
            const uint32_t ac = (uint32_t)(k16 * 2 + (lane >> 4));
            const uint32_t bc = (uint32_t)(k16 * 2 + ((lane & 8) >> 3));
            uint32_t Ah[4][4], Bh[4][2], Bl[4][2];
            #pragma unroll
            for (int am = 0; am < 4; am++)
                ldmx4(Ah[am], aH + sw_off((uint32_t)(warp_m + am * 16) + arow, ac));
            #pragma unroll
            for (int bp = 0; bp < 2; bp++) {     // each x4 = 2 n-atoms
                const uint32_t ro = sw_off((uint32_t)(warp_n + bp * 16) + nrow, bc);
                uint32_t r[4];
                ldmx4(r, bH + ro);
                Bh[bp*2][0]=r[0]; Bh[bp*2][1]=r[1]; Bh[bp*2+1][0]=r[2]; Bh[bp*2+1][1]=r[3];
                ldmx4(r, bL + ro);
                Bl[bp*2][0]=r[0]; Bl[bp*2][1]=r[1]; Bl[bp*2+1][0]=r[2]; Bl[bp*2+1][1]=r[3];
            }
            #pragma unroll
            for (int am = 0; am < 4; am++)
                #pragma unroll
                for (int an = 0; an < 4; an++) {
                    mma16816(acc[am][an], Ah[am], Bh[an]);
                    mma16816(acc[am][an], Ah[am], Bl[an]);
                }
        }
    };

    // ---- 2-stage pipeline, prefetch distance 1
    cpAll(0, sb); cp_commit();

    for (int s = 0; s < NCHUNK; s++) {
        if (s + 1 < NCHUNK) {
            // stage (s+1)&1 was consumed by compute(s-1); barrier at loop end covers it
            cpAll(s + 1, sb + (uint32_t)((s + 1) & 1) * STAGE_B);
            cp_commit();
            cp_wait<1>();       // chunk s complete (chunk s+1 may remain in flight)
        } else {
            cp_wait<0>();
        }
        __syncthreads();        // chunk s visible to all warps
        compute(sb + (uint32_t)(s & 1) * STAGE_B);
        __syncthreads();        // all warps done with stage s&1 before iter s+1 overwrites it
    }

    // ---- epilogue: bias + row mask, float2 stores straight from accumulators
    #pragma unroll
    for (int am = 0; am < 4; am++) {
        const int r1 = row0 + warp_m + am * 16 + (lane >> 2);
        const int r2 = r1 + 8;
        const bool m1 = (mask[r1] != 0u);
        const bool m2 = (mask[r2] != 0u);
        #pragma unroll
        for (int an = 0; an < 4; an++) {
            const int cc = col0 + warp_n + an * 8 + 2 * (lane & 3);
            const float b0 = g_bias[cc], b1 = g_bias[cc + 1];
            float2 v1, v2;
            v1.x = m1 ? acc[am][an][0] + b0 : 0.0f;
            v1.y = m1 ? acc[am][an][1] + b1 : 0.0f;
            v2.x = m2 ? acc[am][an][2] + b0 : 0.0f;
            v2.y = m2 ? acc[am][an][3] + b1 : 0.0f;
            *reinterpret_cast<float2*>(out + (size_t)r1 * TOK + cc) = v1;
            *reinterpret_cast<float2*>(out + (size_t)r2 * TOK + cc) = v2;
        }
    }
}

// ---------------------------------------------------------------------------
extern "C" void kernel_launch(void* const* d_in, const int* in_sizes, int n_in,
                              void* d_out, int out_size)
{
    const float*        emb   = (const float*)d_in[0];
    const float*        vis   = (const float*)d_in[1];
    const float*        bbox  = (const float*)d_in[2];
    const float*        kp    = (const float*)d_in[3];
    const unsigned int* mask  = (const unsigned int*)d_in[4];
    const float*        app_W = (const float*)d_in[5];
    const float*        app_b = (const float*)d_in[6];
    const float*        st_W  = (const float*)d_in[7];
    const float*        st_b  = (const float*)d_in[8];
    float*              out   = (float*)d_out;

    cudaFuncSetAttribute(gemm_hmma, cudaFuncAttributeMaxDynamicSharedMemorySize, SMEM_TOTAL);

    prep_all<<<M_ROWS + TOK, 128>>>(emb, vis, bbox, kp, app_W, app_b, st_W, st_b);

    dim3 grid(TOK / TILE_N, M_ROWS / TILE_M);   // (8, 256): col-fastest -> A-tile L2 reuse
    gemm_hmma<<<grid, 256, SMEM_TOTAL>>>(mask, out);
}